// round 9
// baseline (speedup 1.0000x reference)
#include <cuda_runtime.h>
#include <math.h>

// Problem constants
#define BATCH   8
#define T_SEQ   1024
#define E_DIM   768
#define NH      12
#define HD      64
#define M_TOT   (BATCH * T_SEQ)   // 8192

// ---------------------------------------------------------------------------
// Scratch (device globals — no allocation allowed)
// ---------------------------------------------------------------------------
__device__ float g_q[BATCH * NH * T_SEQ * HD];   // [B,H,T,D]
__device__ float g_k[BATCH * NH * T_SEQ * HD];
__device__ float g_v[BATCH * NH * T_SEQ * HD];
__device__ float g_ctx[BATCH * T_SEQ * E_DIM];   // [B,T,E]

// ---------------------------------------------------------------------------
// TF32 helpers
// ---------------------------------------------------------------------------
__device__ __forceinline__ unsigned f2tf32(float x) {
    unsigned r;
    asm("cvt.rna.tf32.f32 %0, %1;" : "=r"(r) : "f"(x));
    return r;
}

__device__ __forceinline__ void mma_tf32(
    float& c0, float& c1, float& c2, float& c3,
    unsigned a0, unsigned a1, unsigned a2, unsigned a3,
    unsigned b0, unsigned b1)
{
    asm volatile(
        "mma.sync.aligned.m16n8k8.row.col.f32.tf32.tf32.f32 "
        "{%0,%1,%2,%3}, {%4,%5,%6,%7}, {%8,%9}, {%0,%1,%2,%3};"
        : "+f"(c0), "+f"(c1), "+f"(c2), "+f"(c3)
        : "r"(a0), "r"(a1), "r"(a2), "r"(a3), "r"(b0), "r"(b1));
}

// ---------------------------------------------------------------------------
// 2-pass TF32 GEMM (NT): out[m,n] = sum_k A[m,k]*W[n,k] + bias[n]
// A rounded once to tf32 (err ~7e-5 rms); W = Wh + Wl exact split.
// Passes: Ah·Wh + Ah·Wl.
// 128x128 CTA tile, BK=8, 8 warps each 64x32. Double-buffered smem,
// register prefetch, one barrier per k-tile. Smem row pad 12 words
// -> (12*grp+thr) mod 32 all-distinct: conflict-free fragment LDS.
// qkv_mode: 0 -> row-major [M_TOT,768]; 1 -> scatter to [B,H,T,D]
// ---------------------------------------------------------------------------
#define GPADW 12

__device__ __forceinline__ void gemm_tf32_body(
    const float* __restrict__ A,
    const float* __restrict__ W,
    const float* __restrict__ bias,
    float* __restrict__ out,
    int qkv_mode)
{
    __shared__ unsigned Ah[2][128][GPADW];
    __shared__ unsigned Wh[2][128][GPADW];
    __shared__ unsigned Wl[2][128][GPADW];

    const int tid   = threadIdx.x;
    const int lane  = tid & 31;
    const int wid   = tid >> 5;          // 0..7
    const int warpM = wid >> 2;          // 0..1
    const int warpN = wid & 3;           // 0..3
    const int grp   = lane >> 2;         // 0..7
    const int thr   = lane & 3;          // 0..3
    const int m0    = blockIdx.y << 7;
    const int n0    = blockIdx.x << 7;

    float acc[4][4][4];
#pragma unroll
    for (int mt = 0; mt < 4; ++mt)
#pragma unroll
        for (int nt = 0; nt < 4; ++nt)
#pragma unroll
            for (int r = 0; r < 4; ++r) acc[mt][nt][r] = 0.0f;

    const int lrow = tid >> 1;           // 0..127
    const int lcol = (tid & 1) << 2;     // 0 or 4
    const float* Ap = A + (size_t)(m0 + lrow) * E_DIM + lcol;
    const float* Wp = W + (size_t)(n0 + lrow) * E_DIM + lcol;

    auto stage = [&](int b, float4 a4, float4 w4) {
        *(uint4*)&Ah[b][lrow][lcol] = make_uint4(
            f2tf32(a4.x), f2tf32(a4.y), f2tf32(a4.z), f2tf32(a4.w));
        unsigned g0 = f2tf32(w4.x), g1 = f2tf32(w4.y),
                 g2 = f2tf32(w4.z), g3 = f2tf32(w4.w);
        *(uint4*)&Wh[b][lrow][lcol] = make_uint4(g0, g1, g2, g3);
        *(uint4*)&Wl[b][lrow][lcol] = make_uint4(
            f2tf32(w4.x - __uint_as_float(g0)),
            f2tf32(w4.y - __uint_as_float(g1)),
            f2tf32(w4.z - __uint_as_float(g2)),
            f2tf32(w4.w - __uint_as_float(g3)));
    };

    stage(0, *(const float4*)Ap, *(const float4*)Wp);
    __syncthreads();

    const int NTILE = E_DIM / 8;   // 96
    int buf = 0;

    for (int t = 0; t < NTILE; ++t) {
        float4 a4, w4;
        const bool has_next = (t + 1 < NTILE);
        if (has_next) {
            const int k0 = (t + 1) * 8;
            a4 = *(const float4*)(Ap + k0);
            w4 = *(const float4*)(Wp + k0);
        }

        // B fragments (hi + lo)
        unsigned bh0[4], bh1[4], bl0[4], bl1[4];
#pragma unroll
        for (int nt = 0; nt < 4; ++nt) {
            const int n = warpN * 32 + nt * 8 + grp;
            bh0[nt] = Wh[buf][n][thr];
            bh1[nt] = Wh[buf][n][thr + 4];
            bl0[nt] = Wl[buf][n][thr];
            bl1[nt] = Wl[buf][n][thr + 4];
        }
#pragma unroll
        for (int mt = 0; mt < 4; ++mt) {
            const int m = warpM * 64 + mt * 16 + grp;
            unsigned ah0 = Ah[buf][m][thr];
            unsigned ah1 = Ah[buf][m + 8][thr];
            unsigned ah2 = Ah[buf][m][thr + 4];
            unsigned ah3 = Ah[buf][m + 8][thr + 4];
#pragma unroll
            for (int nt = 0; nt < 4; ++nt) {
                mma_tf32(acc[mt][nt][0], acc[mt][nt][1], acc[mt][nt][2], acc[mt][nt][3],
                         ah0, ah1, ah2, ah3, bh0[nt], bh1[nt]);
                mma_tf32(acc[mt][nt][0], acc[mt][nt][1], acc[mt][nt][2], acc[mt][nt][3],
                         ah0, ah1, ah2, ah3, bl0[nt], bl1[nt]);
            }
        }

        if (has_next) {
            const int nb = buf ^ 1;
            stage(nb, a4, w4);
            __syncthreads();
            buf = nb;
        }
    }

    // Epilogue: bias + store
#pragma unroll
    for (int mt = 0; mt < 4; ++mt) {
#pragma unroll
        for (int nt = 0; nt < 4; ++nt) {
            const int mrow = m0 + warpM * 64 + mt * 16 + grp;
            const int ncol = n0 + warpN * 32 + nt * 8 + 2 * thr;
#pragma unroll
            for (int half = 0; half < 2; ++half) {
                const int m = mrow + half * 8;
                const int b = m >> 10;
                const int tt = m & 1023;
#pragma unroll
                for (int c = 0; c < 2; ++c) {
                    const int n = ncol + c;
                    const float v = acc[mt][nt][half * 2 + c] + bias[n];
                    if (qkv_mode) {
                        const int h = n >> 6;
                        const int d = n & 63;
                        out[(((size_t)(b * NH + h) << 10) + tt) * HD + d] = v;
                    } else {
                        out[(size_t)m * E_DIM + n] = v;
                    }
                }
            }
        }
    }
}

__global__ __launch_bounds__(256) void qkv_gemm_kernel(
    const float* __restrict__ x,
    const float* __restrict__ Wq, const float* __restrict__ bq,
    const float* __restrict__ Wk, const float* __restrict__ bk,
    const float* __restrict__ Wv, const float* __restrict__ bv,
    float* __restrict__ q, float* __restrict__ k, float* __restrict__ v)
{
    const int z = blockIdx.z;
    const float* W    = (z == 0) ? Wq : (z == 1) ? Wk : Wv;
    const float* bias = (z == 0) ? bq : (z == 1) ? bk : bv;
    float*       out  = (z == 0) ? q  : (z == 1) ? k  : v;
    gemm_tf32_body(x, W, bias, out, 1);
}

__global__ __launch_bounds__(256) void out_gemm_kernel(
    const float* __restrict__ ctx,
    const float* __restrict__ Wo, const float* __restrict__ bo,
    float* __restrict__ out)
{
    gemm_tf32_body(ctx, Wo, bo, out, 0);
}

// ---------------------------------------------------------------------------
// Flash attention (causal) on tensor cores (tf32 mma).
// Grid: (T/64, B*H), 256 threads = 8 warps; warp = (mtile = wid&3, nhalf = wid>>2).
// S = Qh·Kh (1-pass; Q rounded once, score err ~4e-5 abs);
// PV = PhVh + PhVl (2-pass; P-lo dropped, ~1e-4 err).
// Row stats across the two n-half warps via smem; 4 barriers per k-tile.
// Smem pad 68 words -> conflict-free Q/K/P fragment LDS, 2-way on V.
// Smem = 88064 B -> 2 CTAs/SM.
// ---------------------------------------------------------------------------
#define APAD 68
#define AQH  0
#define AKH  (64 * APAD)
#define AVH  (2 * 64 * APAD)
#define AVL  (3 * 64 * APAD)
#define APH  (4 * 64 * APAD)
#define AST  (5 * 64 * APAD)                 // stats: Rmax[64][2], Rsum[64][2]
#define ATT_SMEM ((AST + 256) * 4)           // 88064 bytes

__global__ __launch_bounds__(256) void attn_kernel(
    const float* __restrict__ q,
    const float* __restrict__ k,
    const float* __restrict__ v,
    float* __restrict__ ctx)
{
    extern __shared__ unsigned smu[];
    float* Rmax = (float*)(smu + AST);
    float* Rsum = Rmax + 128;

    const int tid   = threadIdx.x;
    const int lane  = tid & 31;
    const int wid   = tid >> 5;
    const int warpM = wid & 3;               // m-tile (16 rows)
    const int warpN = wid >> 2;              // n half (32 cols)
    const int grp   = lane >> 2;
    const int thr   = lane & 3;
    const int qt    = blockIdx.x;
    const int bh    = blockIdx.y;

    const size_t base = (size_t)bh * T_SEQ * HD;
    const int lin0 = tid * 4;

    // ---- load Q tile (scaled by 1/8), tf32 into smem ----
    {
        const float* qb = q + base + (size_t)qt * 64 * HD;
#pragma unroll
        for (int il = 0; il < 4; ++il) {
            const int lin = il * 1024 + lin0;
            const int r = lin >> 6, c = lin & 63;
            float4 t4 = *(const float4*)(qb + lin);
            *(uint4*)&smu[AQH + r * APAD + c] = make_uint4(
                f2tf32(t4.x * 0.125f), f2tf32(t4.y * 0.125f),
                f2tf32(t4.z * 0.125f), f2tf32(t4.w * 0.125f));
        }
    }

    // Running stats for this thread's two rows (grp, grp+8 of its m-tile)
    float m0r = -INFINITY, m1r = -INFINITY;
    float l0r = 0.0f, l1r = 0.0f;
    float o[4][4];
#pragma unroll
    for (int nt = 0; nt < 4; ++nt)
#pragma unroll
        for (int r = 0; r < 4; ++r) o[nt][r] = 0.0f;

    const int row0 = warpM * 16 + grp;       // tile-local rows
    const int row1 = row0 + 8;

    // Prefetch K/V tile 0
    float4 kreg[4], vreg[4];
#pragma unroll
    for (int il = 0; il < 4; ++il) {
        kreg[il] = *(const float4*)(k + base + il * 1024 + lin0);
        vreg[il] = *(const float4*)(v + base + il * 1024 + lin0);
    }

    for (int kt = 0; kt <= qt; ++kt) {
        // ---- convert & store K (hi), V (hi+lo) ----
#pragma unroll
        for (int il = 0; il < 4; ++il) {
            const int lin = il * 1024 + lin0;
            const int r = lin >> 6, c = lin & 63;
            *(uint4*)&smu[AKH + r * APAD + c] = make_uint4(
                f2tf32(kreg[il].x), f2tf32(kreg[il].y),
                f2tf32(kreg[il].z), f2tf32(kreg[il].w));
            unsigned vh0 = f2tf32(vreg[il].x), vh1 = f2tf32(vreg[il].y),
                     vh2 = f2tf32(vreg[il].z), vh3 = f2tf32(vreg[il].w);
            *(uint4*)&smu[AVH + r * APAD + c] = make_uint4(vh0, vh1, vh2, vh3);
            *(uint4*)&smu[AVL + r * APAD + c] = make_uint4(
                f2tf32(vreg[il].x - __uint_as_float(vh0)),
                f2tf32(vreg[il].y - __uint_as_float(vh1)),
                f2tf32(vreg[il].z - __uint_as_float(vh2)),
                f2tf32(vreg[il].w - __uint_as_float(vh3)));
        }
        __syncthreads();

        // Prefetch next K/V tile (hides under mma)
        if (kt < qt) {
            const float* kb = k + base + (size_t)(kt + 1) * 64 * HD;
            const float* vb = v + base + (size_t)(kt + 1) * 64 * HD;
#pragma unroll
            for (int il = 0; il < 4; ++il) {
                kreg[il] = *(const float4*)(kb + il * 1024 + lin0);
                vreg[il] = *(const float4*)(vb + il * 1024 + lin0);
            }
        }

        // ---- S = Q·K^T for (m-tile warpM, n-half warpN), single tf32 pass ----
        float s[4][4];
#pragma unroll
        for (int nt = 0; nt < 4; ++nt)
#pragma unroll
            for (int r = 0; r < 4; ++r) s[nt][r] = 0.0f;

#pragma unroll
        for (int ks = 0; ks < 8; ++ks) {
            const int kk = ks * 8;
            unsigned ah0 = smu[AQH + row0 * APAD + kk + thr];
            unsigned ah1 = smu[AQH + row1 * APAD + kk + thr];
            unsigned ah2 = smu[AQH + row0 * APAD + kk + thr + 4];
            unsigned ah3 = smu[AQH + row1 * APAD + kk + thr + 4];
#pragma unroll
            for (int nt = 0; nt < 4; ++nt) {
                const int n = warpN * 32 + nt * 8 + grp;
                unsigned b0 = smu[AKH + n * APAD + kk + thr];
                unsigned b1 = smu[AKH + n * APAD + kk + thr + 4];
                mma_tf32(s[nt][0], s[nt][1], s[nt][2], s[nt][3],
                         ah0, ah1, ah2, ah3, b0, b1);
            }
        }

        // ---- causal mask (diagonal tile only) ----
        if (kt == qt) {
#pragma unroll
            for (int nt = 0; nt < 4; ++nt) {
                const int col = warpN * 32 + nt * 8 + 2 * thr;
                if (col > row0)     s[nt][0] = -INFINITY;
                if (col + 1 > row0) s[nt][1] = -INFINITY;
                if (col > row1)     s[nt][2] = -INFINITY;
                if (col + 1 > row1) s[nt][3] = -INFINITY;
            }
        }

        // ---- row max: local -> quad shfl -> smem combine across n-halves ----
        float mx0 = -INFINITY, mx1 = -INFINITY;
#pragma unroll
        for (int nt = 0; nt < 4; ++nt) {
            mx0 = fmaxf(mx0, fmaxf(s[nt][0], s[nt][1]));
            mx1 = fmaxf(mx1, fmaxf(s[nt][2], s[nt][3]));
        }
        mx0 = fmaxf(mx0, __shfl_xor_sync(0xffffffffu, mx0, 1));
        mx0 = fmaxf(mx0, __shfl_xor_sync(0xffffffffu, mx0, 2));
        mx1 = fmaxf(mx1, __shfl_xor_sync(0xffffffffu, mx1, 1));
        mx1 = fmaxf(mx1, __shfl_xor_sync(0xffffffffu, mx1, 2));
        if (thr == 0) {
            Rmax[row0 * 2 + warpN] = mx0;
            Rmax[row1 * 2 + warpN] = mx1;
        }
        __syncthreads();
        const float tm0 = fmaxf(Rmax[row0 * 2], Rmax[row0 * 2 + 1]);
        const float tm1 = fmaxf(Rmax[row1 * 2], Rmax[row1 * 2 + 1]);

        const float mnew0 = fmaxf(m0r, tm0);
        const float mnew1 = fmaxf(m1r, tm1);
        const float corr0 = __expf(m0r - mnew0);
        const float corr1 = __expf(m1r - mnew1);
        m0r = mnew0; m1r = mnew1;

        // ---- P = exp(s - mnew): write tf32 P, accumulate row sums (fp32) ----
        float sum0 = 0.0f, sum1 = 0.0f;
#pragma unroll
        for (int nt = 0; nt < 4; ++nt) {
            const int col = warpN * 32 + nt * 8 + 2 * thr;
            float p0 = __expf(s[nt][0] - mnew0);
            float p1 = __expf(s[nt][1] - mnew0);
            float p2 = __expf(s[nt][2] - mnew1);
            float p3 = __expf(s[nt][3] - mnew1);
            sum0 += p0 + p1;
            sum1 += p2 + p3;
            smu[APH + row0 * APAD + col]     = f2tf32(p0);
            smu[APH + row0 * APAD + col + 1] = f2tf32(p1);
            smu[APH + row1 * APAD + col]     = f2tf32(p2);
            smu[APH + row1 * APAD + col + 1] = f2tf32(p3);
        }
        sum0 += __shfl_xor_sync(0xffffffffu, sum0, 1);
        sum0 += __shfl_xor_sync(0xffffffffu, sum0, 2);
        sum1 += __shfl_xor_sync(0xffffffffu, sum1, 1);
        sum1 += __shfl_xor_sync(0xffffffffu, sum1, 2);
        if (thr == 0) {
            Rsum[row0 * 2 + warpN] = sum0;
            Rsum[row1 * 2 + warpN] = sum1;
        }
        __syncthreads();
        l0r = l0r * corr0 + Rsum[row0 * 2] + Rsum[row0 * 2 + 1];
        l1r = l1r * corr1 + Rsum[row1 * 2] + Rsum[row1 * 2 + 1];

        // ---- rescale O, then O += P·V (2-pass: Ph·Vh + Ph·Vl) ----
#pragma unroll
        for (int nt = 0; nt < 4; ++nt) {
            o[nt][0] *= corr0; o[nt][1] *= corr0;
            o[nt][2] *= corr1; o[nt][3] *= corr1;
        }
#pragma unroll
        for (int ks = 0; ks < 8; ++ks) {
            const int kk = ks * 8;
            unsigned ph0 = smu[APH + row0 * APAD + kk + thr];
            unsigned ph1 = smu[APH + row1 * APAD + kk + thr];
            unsigned ph2 = smu[APH + row0 * APAD + kk + thr + 4];
            unsigned ph3 = smu[APH + row1 * APAD + kk + thr + 4];
#pragma unroll
            for (int nt = 0; nt < 4; ++nt) {
                const int n = warpN * 32 + nt * 8 + grp;
                unsigned bh0 = smu[AVH + (kk + thr) * APAD + n];
                unsigned bh1 = smu[AVH + (kk + thr + 4) * APAD + n];
                unsigned bl0 = smu[AVL + (kk + thr) * APAD + n];
                unsigned bl1 = smu[AVL + (kk + thr + 4) * APAD + n];
                mma_tf32(o[nt][0], o[nt][1], o[nt][2], o[nt][3],
                         ph0, ph1, ph2, ph3, bh0, bh1);
                mma_tf32(o[nt][0], o[nt][1], o[nt][2], o[nt][3],
                         ph0, ph1, ph2, ph3, bl0, bl1);
            }
        }
        __syncthreads();   // all smem reads done before next tile's stores
    }

    // ---- epilogue: normalize, write ctx [B,T,E] at E = h*64 + d ----
    const int b = bh / NH;
    const int h = bh - b * NH;
    const float inv0 = 1.0f / l0r;
    const float inv1 = 1.0f / l1r;
    const int t0 = qt * 64 + row0;
    const int t1 = qt * 64 + row1;
#pragma unroll
    for (int nt = 0; nt < 4; ++nt) {
        const int d = warpN * 32 + nt * 8 + 2 * thr;
        float* p0 = ctx + ((size_t)(b * T_SEQ + t0)) * E_DIM + h * HD + d;
        float* p1 = ctx + ((size_t)(b * T_SEQ + t1)) * E_DIM + h * HD + d;
        p0[0] = o[nt][0] * inv0;
        p0[1] = o[nt][1] * inv0;
        p1[0] = o[nt][2] * inv1;
        p1[1] = o[nt][3] * inv1;
    }
}

// ---------------------------------------------------------------------------
// Launch
// ---------------------------------------------------------------------------
extern "C" void kernel_launch(void* const* d_in, const int* in_sizes, int n_in,
                              void* d_out, int out_size)
{
    (void)in_sizes; (void)n_in; (void)out_size;
    const float* x  = (const float*)d_in[0];
    const float* Wq = (const float*)d_in[1];
    const float* bq = (const float*)d_in[2];
    const float* Wk = (const float*)d_in[3];
    const float* bk = (const float*)d_in[4];
    const float* Wv = (const float*)d_in[5];
    const float* bv = (const float*)d_in[6];
    const float* Wo = (const float*)d_in[7];
    const float* bo = (const float*)d_in[8];
    float* out = (float*)d_out;

    void *pq, *pk, *pv, *pctx;
    cudaGetSymbolAddress(&pq,  g_q);
    cudaGetSymbolAddress(&pk,  g_k);
    cudaGetSymbolAddress(&pv,  g_v);
    cudaGetSymbolAddress(&pctx, g_ctx);

    cudaFuncSetAttribute(attn_kernel,
                         cudaFuncAttributeMaxDynamicSharedMemorySize, ATT_SMEM);

    dim3 gg(E_DIM / 128, M_TOT / 128, 3);   // (6, 64, 3) — fused QKV
    qkv_gemm_kernel<<<gg, 256>>>(x, Wq, bq, Wk, bk, Wv, bv,
                                 (float*)pq, (float*)pk, (float*)pv);

    dim3 ga(T_SEQ / 64, BATCH * NH);        // (16, 96)
    attn_kernel<<<ga, 256, ATT_SMEM>>>((const float*)pq, (const float*)pk,
                                       (const float*)pv, (float*)pctx);

    dim3 go(E_DIM / 128, M_TOT / 128);      // (6, 64)
    out_gemm_kernel<<<go, 256>>>((const float*)pctx, Wo, bo, out);
}